// round 14
// baseline (speedup 1.0000x reference)
#include <cuda_runtime.h>
#include <cuda_bf16.h>
#include <math.h>
#include <stdint.h>

#define Bb  2
#define Tt  2048
#define Cc  2048
#define Hh  16
#define KVh 4
#define Dd  128
#define REP 4   // Hh / KVh
#define NQKV 3072   // 2048 + 512 + 512

// ---------------- scratch (device globals; no allocation allowed) ----------
__device__ float g_cos[Tt * 64];
__device__ float g_sin[Tt * 64];
__device__ float g_q[(size_t)Bb * Hh  * Tt * Dd];   // (b,h,t,d) fp32 (pre-rope)
__device__ float g_k[(size_t)Bb * KVh * Tt * Dd];
__device__ float g_v[(size_t)Bb * KVh * Tt * Dd];
__device__ float g_att[(size_t)Bb * Tt * Cc];       // (b*t, h*d) row-major

// bf16 hi/lo split operands
__device__ __nv_bfloat16 g_qh[(size_t)Bb * Hh  * Tt * Dd];
__device__ __nv_bfloat16 g_ql[(size_t)Bb * Hh  * Tt * Dd];
__device__ __nv_bfloat16 g_kh[(size_t)Bb * KVh * Tt * Dd];
__device__ __nv_bfloat16 g_kl[(size_t)Bb * KVh * Tt * Dd];
__device__ __nv_bfloat16 g_vh[(size_t)Bb * KVh * Tt * Dd];
__device__ __nv_bfloat16 g_vl[(size_t)Bb * KVh * Tt * Dd];
__device__ __nv_bfloat16 g_xh[(size_t)Bb * Tt * Cc];
__device__ __nv_bfloat16 g_xl[(size_t)Bb * Tt * Cc];
__device__ __nv_bfloat16 g_wh[(size_t)NQKV * Cc];
__device__ __nv_bfloat16 g_wl[(size_t)NQKV * Cc];
__device__ __nv_bfloat16 g_woh[(size_t)Cc * Cc];
__device__ __nv_bfloat16 g_wol[(size_t)Cc * Cc];
__device__ __nv_bfloat16 g_ah[(size_t)Bb * Tt * Cc];
__device__ __nv_bfloat16 g_al[(size_t)Bb * Tt * Cc];

// ---------------- RoPE tables ----------------------------------------------
__global__ void rope_tables_kernel() {
    int idx = blockIdx.x * blockDim.x + threadIdx.x;
    if (idx >= Tt * 64) return;
    int t = idx / 64, i = idx % 64;
    double inv = pow(10000.0, -(double)(2 * i) / 128.0);
    double ang = (double)t * inv;
    g_cos[idx] = (float)cos(ang);
    g_sin[idx] = (float)sin(ang);
}

// ======================= helpers ===========================================
__device__ __forceinline__ uint32_t smem_u32_(const void* p) {
    uint32_t a;
    asm("{ .reg .u64 t; cvta.to.shared.u64 t, %1; cvt.u32.u64 %0, t; }"
        : "=r"(a) : "l"(p));
    return a;
}
__device__ __forceinline__ uint32_t pack_bf16x2(float lo, float hi) {
    uint32_t r;
    asm("cvt.rn.bf16x2.f32 %0, %1, %2;" : "=r"(r) : "f"(hi), "f"(lo));
    return r;
}
__device__ __forceinline__ void mma16816b(float* c, const uint32_t* a,
                                          uint32_t b0, uint32_t b1) {
    asm volatile(
        "mma.sync.aligned.m16n8k16.row.col.f32.bf16.bf16.f32 "
        "{%0,%1,%2,%3}, {%4,%5,%6,%7}, {%8,%9}, {%0,%1,%2,%3};"
        : "+f"(c[0]), "+f"(c[1]), "+f"(c[2]), "+f"(c[3])
        : "r"(a[0]), "r"(a[1]), "r"(a[2]), "r"(a[3]), "r"(b0), "r"(b1));
}
__device__ __forceinline__ void ldsm_x4(uint32_t& r0, uint32_t& r1, uint32_t& r2,
                                        uint32_t& r3, uint32_t addr) {
    asm volatile("ldmatrix.sync.aligned.m8n8.x4.shared.b16 {%0,%1,%2,%3}, [%4];"
                 : "=r"(r0), "=r"(r1), "=r"(r2), "=r"(r3) : "r"(addr));
}
__device__ __forceinline__ void ldsm_x4_t(uint32_t& r0, uint32_t& r1, uint32_t& r2,
                                          uint32_t& r3, uint32_t addr) {
    asm volatile("ldmatrix.sync.aligned.m8n8.x4.trans.shared.b16 {%0,%1,%2,%3}, [%4];"
                 : "=r"(r0), "=r"(r1), "=r"(r2), "=r"(r3) : "r"(addr));
}
__device__ __forceinline__ void cp16(uint32_t dst, const void* src) {
    asm volatile("cp.async.cg.shared.global [%0], [%1], 16;" :: "r"(dst), "l"(src));
}
#define CP_COMMIT() asm volatile("cp.async.commit_group;" ::: "memory")
#define CP_WAIT(n)  asm volatile("cp.async.wait_group %0;" :: "n"(n) : "memory")

// ---------------- split conversions -----------------------------------------
__global__ void split_f32_kernel(const float* __restrict__ src,
                                 __nv_bfloat16* __restrict__ dh,
                                 __nv_bfloat16* __restrict__ dl, int n) {
    int i = blockIdx.x * blockDim.x + threadIdx.x;
    if (i >= n) return;
    float y = src[i];
    __nv_bfloat16 h = __float2bfloat16(y);
    dh[i] = h;
    dl[i] = __float2bfloat16(y - __bfloat162float(h));
}

__global__ void split_weights_kernel(const float* __restrict__ Wq,
                                     const float* __restrict__ Wk,
                                     const float* __restrict__ Wv,
                                     const float* __restrict__ Wo) {
    const int nq = 2048 * Cc;
    const int nk = 512 * Cc;
    const int nqkv = nq + 2 * nk;
    const int ntot = nqkv + Cc * Cc;
    int idx = blockIdx.x * blockDim.x + threadIdx.x;
    if (idx >= ntot) return;
    float y;
    __nv_bfloat16* dh;
    __nv_bfloat16* dl;
    int o;
    if (idx < nq)               { y = Wq[idx];            dh = g_wh;  dl = g_wl;  o = idx; }
    else if (idx < nq + nk)     { y = Wk[idx - nq];       dh = g_wh;  dl = g_wl;  o = idx; }
    else if (idx < nqkv)        { y = Wv[idx - nq - nk];  dh = g_wh;  dl = g_wl;  o = idx; }
    else                        { y = Wo[idx - nqkv];     dh = g_woh; dl = g_wol; o = idx - nqkv; }
    __nv_bfloat16 h = __float2bfloat16(y);
    dh[o] = h;
    dl[o] = __float2bfloat16(y - __bfloat162float(h));
}

__global__ void postproc_kernel(float qscale) {
    const int N1 = Bb * Hh  * Tt * 64;
    const int N2 = Bb * KVh * Tt * 64;
    const int N3 = Bb * KVh * Tt * Dd;
    int idx = blockIdx.x * blockDim.x + threadIdx.x;
    if (idx < N1 + N2) {
        const float* src; __nv_bfloat16 *dh, *dl; float scale; int r;
        if (idx < N1) { src = g_q; dh = g_qh; dl = g_ql; scale = qscale; r = idx; }
        else          { src = g_k; dh = g_kh; dl = g_kl; scale = 1.0f;  r = idx - N1; }
        int d  = r & 63;
        int t  = (r >> 6) & (Tt - 1);
        int bh = r / (64 * Tt);
        float c = g_cos[t * 64 + d];
        float s = g_sin[t * 64 + d];
        size_t base = ((size_t)bh * Tt + t) * Dd;
        float x1 = src[base + d], x2 = src[base + d + 64];
        float y1 = (x1 * c - x2 * s) * scale;
        float y2 = (x2 * c + x1 * s) * scale;
        __nv_bfloat16 h1 = __float2bfloat16(y1);
        __nv_bfloat16 h2 = __float2bfloat16(y2);
        dh[base + d]      = h1;
        dh[base + d + 64] = h2;
        dl[base + d]      = __float2bfloat16(y1 - __bfloat162float(h1));
        dl[base + d + 64] = __float2bfloat16(y2 - __bfloat162float(h2));
    } else if (idx < N1 + N2 + N3) {
        int r = idx - N1 - N2;
        float y = g_v[r];
        __nv_bfloat16 h = __float2bfloat16(y);
        g_vh[r] = h;
        g_vl[r] = __float2bfloat16(y - __bfloat162float(h));
    }
}

// ============ bf16 hi/lo GEMM — flash-shaped: 128 thr, M64xN128, occ 2 ======
#define G2LDH 40                       // smem stride in halves (32 + 8 pad, 80B = 16B-aligned)
#define G2_A  (64 * G2LDH * 2)         // 5120 B per A matrix
#define G2_B  (128 * G2LDH * 2)       // 10240 B per B matrix
#define G2STG (2 * G2_A + 2 * G2_B)    // 30720 B per stage

template <int MODE>
__global__ void __launch_bounds__(128, 2)
gemm_bf16_kernel(const __nv_bfloat16* __restrict__ Ah,
                 const __nv_bfloat16* __restrict__ Al,
                 const __nv_bfloat16* __restrict__ Bh,
                 const __nv_bfloat16* __restrict__ Bl,
                 float* __restrict__ Cq, float* __restrict__ Ck,
                 float* __restrict__ Cv, int M, int N, int K)
{
    extern __shared__ char smem[];
    const uint32_t sb = smem_u32_(smem);

    const int tid  = threadIdx.x;
    const int wid  = tid >> 5;          // 0..3, owns 32-col N slice
    const int lane = tid & 31;
    const int m0   = blockIdx.y * 64;
    const int n0   = blockIdx.x * 128;

    // load mapping: A row tid>>1 (2 threads/row), B row tid (1 thread/row)
    const int arow = tid >> 1;
    const int acol = (tid & 1) * 16;    // halves
    const size_t aoff = (size_t)(m0 + arow) * K + acol;
    const uint32_t a_smo = (uint32_t)(arow * G2LDH + acol) * 2;
    const size_t boff = (size_t)(n0 + tid) * K;
    const uint32_t b_smo = (uint32_t)(tid * G2LDH) * 2;

    auto load_stage = [&](int kk, int stg) {
        const uint32_t db = sb + stg * G2STG;
        cp16(db + a_smo,             Ah + aoff + kk);
        cp16(db + a_smo + 16,        Ah + aoff + kk + 8);
        cp16(db + G2_A + a_smo,      Al + aoff + kk);
        cp16(db + G2_A + a_smo + 16, Al + aoff + kk + 8);
        const uint32_t bb = db + 2 * G2_A + b_smo;
        cp16(bb,      Bh + boff + kk);
        cp16(bb + 16, Bh + boff + kk + 8);
        cp16(bb + 32, Bh + boff + kk + 16);
        cp16(bb + 48, Bh + boff + kk + 24);
        const uint32_t bb2 = bb + G2_B;
        cp16(bb2,      Bl + boff + kk);
        cp16(bb2 + 16, Bl + boff + kk + 8);
        cp16(bb2 + 32, Bl + boff + kk + 16);
        cp16(bb2 + 48, Bl + boff + kk + 24);
    };

    float acc[4][4][4];
#pragma unroll
    for (int i = 0; i < 4; i++)
#pragma unroll
        for (int j = 0; j < 4; j++)
#pragma unroll
            for (int q = 0; q < 4; q++) acc[i][j][q] = 0.f;

    const int NC = K / 32;

    load_stage(0, 0);
    CP_COMMIT();

    const uint32_t a_rl  = lane & 15;
    const uint32_t a_kh  = (lane >> 4) * 8;
    const uint32_t b_r2  = (lane & 7) + ((lane >> 4) * 8);
    const uint32_t b_kh  = ((lane >> 3) & 1) * 8;

    for (int i = 0; i < NC; i++) {
        if (i + 1 < NC) {
            load_stage((i + 1) * 32, (i + 1) & 1);
            CP_COMMIT();
            CP_WAIT(1);
        } else {
            CP_WAIT(0);
        }
        __syncthreads();

        const uint32_t stb = sb + (i & 1) * G2STG;
#pragma unroll
        for (int kstep = 0; kstep < 2; kstep++) {
            const uint32_t kof = kstep * 16;

            // B fragments (warp's 32-col slice), hi and lo
            uint32_t bh[4][2], bl[4][2];
#pragma unroll
            for (int p = 0; p < 2; p++) {
                uint32_t bd = stb + 2 * G2_A
                            + ((wid * 32 + p * 16 + b_r2) * G2LDH + kof + b_kh) * 2;
                ldsm_x4(bh[2*p][0], bh[2*p][1], bh[2*p+1][0], bh[2*p+1][1], bd);
                ldsm_x4(bl[2*p][0], bl[2*p][1], bl[2*p+1][0], bl[2*p+1][1], bd + G2_B);
            }

            // Phase 1: A-hi, passes hi*hi and hi*lo
            uint32_t af[4][4];
#pragma unroll
            for (int mt = 0; mt < 4; mt++) {
                uint32_t ad = stb + ((mt * 16 + a_rl) * G2LDH + kof + a_kh) * 2;
                ldsm_x4(af[mt][0], af[mt][1], af[mt][2], af[mt][3], ad);
            }
#pragma unroll
            for (int mt = 0; mt < 4; mt++)
#pragma unroll
                for (int nt = 0; nt < 4; nt++) {
                    mma16816b(acc[mt][nt], af[mt], bh[nt][0], bh[nt][1]);
                    mma16816b(acc[mt][nt], af[mt], bl[nt][0], bl[nt][1]);
                }
            // Phase 2: A-lo, pass lo*hi
#pragma unroll
            for (int mt = 0; mt < 4; mt++) {
                uint32_t ad = stb + G2_A + ((mt * 16 + a_rl) * G2LDH + kof + a_kh) * 2;
                ldsm_x4(af[mt][0], af[mt][1], af[mt][2], af[mt][3], ad);
            }
#pragma unroll
            for (int mt = 0; mt < 4; mt++)
#pragma unroll
                for (int nt = 0; nt < 4; nt++)
                    mma16816b(acc[mt][nt], af[mt], bh[nt][0], bh[nt][1]);
        }
        __syncthreads();
    }

    // epilogue
#pragma unroll
    for (int mt = 0; mt < 4; mt++) {
        const int r0 = m0 + mt * 16 + (lane >> 2);
        const int r1 = r0 + 8;
#pragma unroll
        for (int nt = 0; nt < 4; nt++) {
            const int c = n0 + wid * 32 + nt * 8 + (lane & 3) * 2;
            if (MODE == 0) {
                *(float2*)(Cq + (size_t)r0 * N + c) = make_float2(acc[mt][nt][0], acc[mt][nt][1]);
                *(float2*)(Cq + (size_t)r1 * N + c) = make_float2(acc[mt][nt][2], acc[mt][nt][3]);
            } else {
                const int b0_ = r0 / Tt, t0_ = r0 & (Tt - 1);
                const int b1_ = r1 / Tt, t1_ = r1 & (Tt - 1);
                float* d0;
                float* d1;
                if (c < 2048) {
                    const int h = c >> 7, d = c & 127;
                    d0 = Cq + (((size_t)b0_ * Hh + h) * Tt + t0_) * Dd + d;
                    d1 = Cq + (((size_t)b1_ * Hh + h) * Tt + t1_) * Dd + d;
                } else if (c < 2560) {
                    const int cc = c - 2048, h = cc >> 7, d = cc & 127;
                    d0 = Ck + (((size_t)b0_ * KVh + h) * Tt + t0_) * Dd + d;
                    d1 = Ck + (((size_t)b1_ * KVh + h) * Tt + t1_) * Dd + d;
                } else {
                    const int cc = c - 2560, h = cc >> 7, d = cc & 127;
                    d0 = Cv + (((size_t)b0_ * KVh + h) * Tt + t0_) * Dd + d;
                    d1 = Cv + (((size_t)b1_ * KVh + h) * Tt + t1_) * Dd + d;
                }
                *(float2*)d0 = make_float2(acc[mt][nt][0], acc[mt][nt][1]);
                *(float2*)d1 = make_float2(acc[mt][nt][2], acc[mt][nt][3]);
            }
        }
    }
}

// ================= HMMA flash attention, occ 2 (unchanged) ==================
#define FC_LDH  136
#define FC_ROW  (FC_LDH * 2)
#define FC_MAT  (64 * FC_ROW)
#define FC_STG  (4 * FC_MAT)
#define FC_QOFF FC_STG
#define FC_SMEM (FC_QOFF + 2 * FC_MAT) // 104448

__global__ void __launch_bounds__(128, 2)
flash_hmma3_kernel() {
    extern __shared__ char smem[];
    const uint32_t sb = smem_u32_(smem);

    const int it = (Tt / 64 - 1) - blockIdx.x;
    const int h  = blockIdx.y;
    const int b  = blockIdx.z;
    const int kvh = h / REP;

    const __nv_bfloat16* qh = g_qh + (((size_t)b * Hh + h) * Tt + it * 64) * Dd;
    const __nv_bfloat16* ql = g_ql + (((size_t)b * Hh + h) * Tt + it * 64) * Dd;
    const __nv_bfloat16* kh = g_kh + ((size_t)b * KVh + kvh) * Tt * Dd;
    const __nv_bfloat16* kl = g_kl + ((size_t)b * KVh + kvh) * Tt * Dd;
    const __nv_bfloat16* vh = g_vh + ((size_t)b * KVh + kvh) * Tt * Dd;
    const __nv_bfloat16* vl = g_vl + ((size_t)b * KVh + kvh) * Tt * Dd;

    const int tid  = threadIdx.x;
    const int wq   = tid >> 5;
    const int lane = tid & 31;

#pragma unroll
    for (int c = tid; c < 1024; c += 128) {
        const uint32_t d = sb + FC_QOFF + (c >> 4) * FC_ROW + (c & 15) * 16;
        const size_t  o = (size_t)(c >> 4) * Dd + (c & 15) * 8;
        cp16(d, qh + o);
        cp16(d + FC_MAT, ql + o);
    }
    CP_COMMIT();
    CP_WAIT(0);
    __syncthreads();

    uint32_t qfh[8][4], qfl[8][4];
    {
        const uint32_t qa = sb + FC_QOFF + (wq * 16 + (lane & 15)) * FC_ROW
                          + ((lane >> 4) * 8) * 2;
#pragma unroll
        for (int ks = 0; ks < 8; ks++) {
            uint32_t ad = qa + ks * 32;
            ldsm_x4(qfh[ks][0], qfh[ks][1], qfh[ks][2], qfh[ks][3], ad);
            ldsm_x4(qfl[ks][0], qfl[ks][1], qfl[ks][2], qfl[ks][3], ad + FC_MAT);
        }
    }

    float m_a = -1e30f, m_b = -1e30f, l_a = 0.f, l_b = 0.f;
    float oacc[16][4];
#pragma unroll
    for (int nt = 0; nt < 16; nt++)
#pragma unroll
        for (int q = 0; q < 4; q++) oacc[nt][q] = 0.f;

    const uint32_t kb_row = (lane & 7) + ((lane >> 4) * 8);
    const uint32_t kb_kh  = ((lane >> 3) & 1) * 8;
    const uint32_t vt_kv  = lane & 15;
    const uint32_t vt_dh  = (lane >> 4) * 8;

    for (int jt = 0; jt <= it; jt++) {
        __syncthreads();
#pragma unroll
        for (int c = tid; c < 1024; c += 128) {
            const uint32_t d = sb + (c >> 4) * FC_ROW + (c & 15) * 16;
            const size_t  o = (size_t)jt * 64 * Dd + (c >> 4) * Dd + (c & 15) * 8;
            cp16(d + 0 * FC_MAT, kh + o);
            cp16(d + 1 * FC_MAT, kl + o);
            cp16(d + 2 * FC_MAT, vh + o);
            cp16(d + 3 * FC_MAT, vl + o);
        }
        CP_COMMIT();
        CP_WAIT(0);
        __syncthreads();

        float sacc[8][4];
#pragma unroll
        for (int nt = 0; nt < 8; nt++)
#pragma unroll
            for (int q = 0; q < 4; q++) sacc[nt][q] = 0.f;

#pragma unroll
        for (int ks = 0; ks < 8; ks++) {
#pragma unroll
            for (int ntp = 0; ntp < 4; ntp++) {
                uint32_t bd = sb + ((ntp * 16 + kb_row) * FC_LDH + ks * 16 + kb_kh) * 2;
                uint32_t k0, k1, k2, k3, c0, c1, c2, c3;
                ldsm_x4(k0, k1, k2, k3, bd + 0 * FC_MAT);
                ldsm_x4(c0, c1, c2, c3, bd + 1 * FC_MAT);
                mma16816b(sacc[2*ntp],   qfh[ks], k0, k1);
                mma16816b(sacc[2*ntp],   qfh[ks], c0, c1);
                mma16816b(sacc[2*ntp],   qfl[ks], k0, k1);
                mma16816b(sacc[2*ntp+1], qfh[ks], k2, k3);
                mma16816b(sacc[2*ntp+1], qfh[ks], c2, c3);
                mma16816b(sacc[2*ntp+1], qfl[ks], k2, k3);
            }
        }

        if (jt == it) {
            const int ra = wq * 16 + (lane >> 2);
            const int cb = (lane & 3) * 2;
#pragma unroll
            for (int nt = 0; nt < 8; nt++) {
                const int c0 = cb + nt * 8;
                if (c0 > ra)         sacc[nt][0] = -1e30f;
                if (c0 + 1 > ra)     sacc[nt][1] = -1e30f;
                if (c0 > ra + 8)     sacc[nt][2] = -1e30f;
                if (c0 + 1 > ra + 8) sacc[nt][3] = -1e30f;
            }
        }

        float mx_a = -1e30f, mx_b = -1e30f;
#pragma unroll
        for (int nt = 0; nt < 8; nt++) {
            mx_a = fmaxf(mx_a, fmaxf(sacc[nt][0], sacc[nt][1]));
            mx_b = fmaxf(mx_b, fmaxf(sacc[nt][2], sacc[nt][3]));
        }
        mx_a = fmaxf(mx_a, __shfl_xor_sync(0xffffffffu, mx_a, 1));
        mx_a = fmaxf(mx_a, __shfl_xor_sync(0xffffffffu, mx_a, 2));
        mx_b = fmaxf(mx_b, __shfl_xor_sync(0xffffffffu, mx_b, 1));
        mx_b = fmaxf(mx_b, __shfl_xor_sync(0xffffffffu, mx_b, 2));

        const float mn_a = fmaxf(m_a, mx_a);
        const float mn_b = fmaxf(m_b, mx_b);
        const float al_a = exp2f(m_a - mn_a);
        const float al_b = exp2f(m_b - mn_b);
        m_a = mn_a; m_b = mn_b;

        float ls_a = 0.f, ls_b = 0.f;
#pragma unroll
        for (int nt = 0; nt < 8; nt++) {
            float p0 = exp2f(sacc[nt][0] - mn_a);
            float p1 = exp2f(sacc[nt][1] - mn_a);
            float p2 = exp2f(sacc[nt][2] - mn_b);
            float p3 = exp2f(sacc[nt][3] - mn_b);
            sacc[nt][0] = p0; sacc[nt][1] = p1; sacc[nt][2] = p2; sacc[nt][3] = p3;
            ls_a += p0 + p1; ls_b += p2 + p3;
        }
        ls_a += __shfl_xor_sync(0xffffffffu, ls_a, 1);
        ls_a += __shfl_xor_sync(0xffffffffu, ls_a, 2);
        ls_b += __shfl_xor_sync(0xffffffffu, ls_b, 1);
        ls_b += __shfl_xor_sync(0xffffffffu, ls_b, 2);
        l_a = l_a * al_a + ls_a;
        l_b = l_b * al_b + ls_b;

#pragma unroll
        for (int nt = 0; nt < 16; nt++) {
            oacc[nt][0] *= al_a; oacc[nt][1] *= al_a;
            oacc[nt][2] *= al_b; oacc[nt][3] *= al_b;
        }

#pragma unroll
        for (int kt = 0; kt < 4; kt++) {
            uint32_t phi[4], plo[4];
            {
                float* pa = sacc[2*kt];
                float* pb = sacc[2*kt + 1];
                __nv_bfloat16 e0, e1;
                e0 = __float2bfloat16(pa[0]); e1 = __float2bfloat16(pa[1]);
                phi[0] = ((uint32_t)__bfloat16_as_ushort(e1) << 16) | __bfloat16_as_ushort(e0);
                plo[0] = pack_bf16x2(pa[0] - __bfloat162float(e0), pa[1] - __bfloat162float(e1));
                e0 = __float2bfloat16(pa[2]); e1 = __float2bfloat16(pa[3]);
                phi[1] = ((uint32_t)__bfloat16_as_ushort(e1) << 16) | __bfloat16_as_ushort(e0);
                plo[1] = pack_bf16x2(pa[2] - __bfloat162float(e0), pa[3] - __bfloat162float(e1));
                e0 = __float2bfloat16(pb[0]); e1 = __float2bfloat16(pb[1]);
                phi[2] = ((uint32_t)__bfloat16_as_ushort(e1) << 16) | __bfloat16_as_ushort(e0);
                plo[2] = pack_bf16x2(pb[0] - __bfloat162float(e0), pb[1] - __bfloat162float(e1));
                e0 = __float2bfloat16(pb[2]); e1 = __float2bfloat16(pb[3]);
                phi[3] = ((uint32_t)__bfloat16_as_ushort(e1) << 16) | __bfloat16_as_ushort(e0);
                plo[3] = pack_bf16x2(pb[2] - __bfloat162float(e0), pb[3] - __bfloat162float(e1));
            }
#pragma unroll
            for (int ntp = 0; ntp < 8; ntp++) {
                uint32_t vd = sb + ((kt * 16 + vt_kv) * FC_LDH + ntp * 16 + vt_dh) * 2;
                uint32_t v0, v1, v2, v3, w0, w1, w2, w3;
                ldsm_x4_t(v0, v1, v2, v3, vd + 2 * FC_MAT);
                ldsm_x4_t(w0, w1, w2, w3, vd + 3 * FC_MAT);
                mma16816b(oacc[2*ntp],   phi, v0, v1);
                mma16816b(oacc[2*ntp],   phi, w0, w1);
                mma16816b(oacc[2*ntp],   plo, v0, v1);
                mma16816b(oacc[2*ntp+1], phi, v2, v3);
                mma16816b(oacc[2*ntp+1], phi, w2, w3);
                mma16816b(oacc[2*ntp+1], plo, v2, v3);
            }
        }
    }

    const float inv_a = 1.f / l_a;
    const float inv_b = 1.f / l_b;
    const int ta = it * 64 + wq * 16 + (lane >> 2);
    const int tb = ta + 8;
    float* opa = g_att + ((size_t)b * Tt + ta) * Cc + h * Dd;
    float* opb = g_att + ((size_t)b * Tt + tb) * Cc + h * Dd;
#pragma unroll
    for (int nt = 0; nt < 16; nt++) {
        const int d = nt * 8 + (lane & 3) * 2;
        *(float2*)(opa + d) = make_float2(oacc[nt][0] * inv_a, oacc[nt][1] * inv_a);
        *(float2*)(opb + d) = make_float2(oacc[nt][2] * inv_b, oacc[nt][3] * inv_b);
    }
}

// ---------------- launch ----------------------------------------------------
extern "C" void kernel_launch(void* const* d_in, const int* in_sizes, int n_in,
                              void* d_out, int out_size) {
    const float* x  = (const float*)d_in[0];
    const float* Wq = (const float*)d_in[1];
    const float* Wk = (const float*)d_in[2];
    const float* Wv = (const float*)d_in[3];
    const float* Wo = (const float*)d_in[4];
    float* out = (float*)d_out;

    float *pq, *pk, *pv, *patt;
    cudaGetSymbolAddress((void**)&pq,   g_q);
    cudaGetSymbolAddress((void**)&pk,   g_k);
    cudaGetSymbolAddress((void**)&pv,   g_v);
    cudaGetSymbolAddress((void**)&patt, g_att);
    __nv_bfloat16 *pxh, *pxl, *pwh, *pwl, *pwoh, *pwol, *pah, *pal;
    cudaGetSymbolAddress((void**)&pxh, g_xh);
    cudaGetSymbolAddress((void**)&pxl, g_xl);
    cudaGetSymbolAddress((void**)&pwh, g_wh);
    cudaGetSymbolAddress((void**)&pwl, g_wl);
    cudaGetSymbolAddress((void**)&pwoh, g_woh);
    cudaGetSymbolAddress((void**)&pwol, g_wol);
    cudaGetSymbolAddress((void**)&pah, g_ah);
    cudaGetSymbolAddress((void**)&pal, g_al);

    const int M = Bb * Tt;                 // 4096
    const int gemm_smem = 2 * G2STG;       // 61440
    cudaFuncSetAttribute(gemm_bf16_kernel<0>,
                         cudaFuncAttributeMaxDynamicSharedMemorySize, gemm_smem);
    cudaFuncSetAttribute(gemm_bf16_kernel<1>,
                         cudaFuncAttributeMaxDynamicSharedMemorySize, gemm_smem);
    cudaFuncSetAttribute(flash_hmma3_kernel,
                         cudaFuncAttributeMaxDynamicSharedMemorySize, FC_SMEM);

    const int nx = M * Cc;
    const float qscale = 0.08838834764831845f * 1.4426950408889634f;

    // launch 0: split x
    split_f32_kernel<<<(nx + 255) / 256, 256>>>(x, pxh, pxl, nx);
    // launch 1: split all weights
    split_weights_kernel<<<((NQKV * Cc + Cc * Cc) + 255) / 256, 256>>>(Wq, Wk, Wv, Wo);
    // launch 2: rope tables
    rope_tables_kernel<<<(Tt * 64 + 255) / 256, 256>>>();
    // launch 3: fused QKV projection (flash-shaped GEMM)
    gemm_bf16_kernel<1><<<dim3(NQKV / 128, M / 64), 128, gemm_smem>>>(
        pxh, pxl, pwh, pwl, pq, pk, pv, M, NQKV, Cc);
    // launch 4: rope + split q/k, split v
    postproc_kernel<<<((Bb*Hh*Tt*64 + Bb*KVh*Tt*64 + Bb*KVh*Tt*Dd) + 255) / 256, 256>>>(qscale);
    // launch 5: flash attention (profiled by ncu -s 5 -c 1)
    flash_hmma3_kernel<<<dim3(Tt / 64, Hh, Bb), 128, FC_SMEM>>>();
    // launch 6: split att
    split_f32_kernel<<<(nx + 255) / 256, 256>>>(patt, pah, pal, nx);
    // launch 7: output projection
    gemm_bf16_kernel<0><<<dim3(Cc / 128, M / 64), 128, gemm_smem>>>(
        pah, pal, pwoh, pwol, out, nullptr, nullptr, M, Cc, Cc);
}

// round 16
// speedup vs baseline: 1.7912x; 1.7912x over previous
#include <cuda_runtime.h>
#include <cuda_bf16.h>
#include <math.h>
#include <stdint.h>

#define Bb  2
#define Tt  2048
#define Cc  2048
#define Hh  16
#define KVh 4
#define Dd  128
#define REP 4   // Hh / KVh
#define NQKV 3072   // 2048 + 512 + 512

// ---------------- scratch (device globals; no allocation allowed) ----------
__device__ float g_cos[Tt * 64];
__device__ float g_sin[Tt * 64];
__device__ float g_q[(size_t)Bb * Hh  * Tt * Dd];   // (b,h,t,d) fp32 (pre-rope)
__device__ float g_k[(size_t)Bb * KVh * Tt * Dd];
__device__ float g_v[(size_t)Bb * KVh * Tt * Dd];

// bf16 hi/lo split operands
__device__ __nv_bfloat16 g_qh[(size_t)Bb * Hh  * Tt * Dd];
__device__ __nv_bfloat16 g_ql[(size_t)Bb * Hh  * Tt * Dd];
__device__ __nv_bfloat16 g_kh[(size_t)Bb * KVh * Tt * Dd];
__device__ __nv_bfloat16 g_kl[(size_t)Bb * KVh * Tt * Dd];
__device__ __nv_bfloat16 g_vh[(size_t)Bb * KVh * Tt * Dd];
__device__ __nv_bfloat16 g_vl[(size_t)Bb * KVh * Tt * Dd];
__device__ __nv_bfloat16 g_xh[(size_t)Bb * Tt * Cc];
__device__ __nv_bfloat16 g_xl[(size_t)Bb * Tt * Cc];
__device__ __nv_bfloat16 g_wh[(size_t)NQKV * Cc];
__device__ __nv_bfloat16 g_wl[(size_t)NQKV * Cc];
__device__ __nv_bfloat16 g_woh[(size_t)Cc * Cc];
__device__ __nv_bfloat16 g_wol[(size_t)Cc * Cc];
__device__ __nv_bfloat16 g_ah[(size_t)Bb * Tt * Cc];   // attention out (hi)
__device__ __nv_bfloat16 g_al[(size_t)Bb * Tt * Cc];   // attention out (lo)

// ---------------- RoPE tables ----------------------------------------------
__global__ void rope_tables_kernel() {
    int idx = blockIdx.x * blockDim.x + threadIdx.x;
    if (idx >= Tt * 64) return;
    int t = idx / 64, i = idx % 64;
    double inv = pow(10000.0, -(double)(2 * i) / 128.0);
    double ang = (double)t * inv;
    g_cos[idx] = (float)cos(ang);
    g_sin[idx] = (float)sin(ang);
}

// ======================= helpers ===========================================
__device__ __forceinline__ uint32_t smem_u32_(const void* p) {
    uint32_t a;
    asm("{ .reg .u64 t; cvta.to.shared.u64 t, %1; cvt.u32.u64 %0, t; }"
        : "=r"(a) : "l"(p));
    return a;
}
__device__ __forceinline__ uint32_t pack_bf16x2(float lo, float hi) {
    uint32_t r;
    asm("cvt.rn.bf16x2.f32 %0, %1, %2;" : "=r"(r) : "f"(hi), "f"(lo));
    return r;
}
__device__ __forceinline__ void mma16816b(float* c, const uint32_t* a,
                                          uint32_t b0, uint32_t b1) {
    asm volatile(
        "mma.sync.aligned.m16n8k16.row.col.f32.bf16.bf16.f32 "
        "{%0,%1,%2,%3}, {%4,%5,%6,%7}, {%8,%9}, {%0,%1,%2,%3};"
        : "+f"(c[0]), "+f"(c[1]), "+f"(c[2]), "+f"(c[3])
        : "r"(a[0]), "r"(a[1]), "r"(a[2]), "r"(a[3]), "r"(b0), "r"(b1));
}
__device__ __forceinline__ void ldsm_x4(uint32_t& r0, uint32_t& r1, uint32_t& r2,
                                        uint32_t& r3, uint32_t addr) {
    asm volatile("ldmatrix.sync.aligned.m8n8.x4.shared.b16 {%0,%1,%2,%3}, [%4];"
                 : "=r"(r0), "=r"(r1), "=r"(r2), "=r"(r3) : "r"(addr));
}
__device__ __forceinline__ void ldsm_x4_t(uint32_t& r0, uint32_t& r1, uint32_t& r2,
                                          uint32_t& r3, uint32_t addr) {
    asm volatile("ldmatrix.sync.aligned.m8n8.x4.trans.shared.b16 {%0,%1,%2,%3}, [%4];"
                 : "=r"(r0), "=r"(r1), "=r"(r2), "=r"(r3) : "r"(addr));
}
__device__ __forceinline__ void cp16(uint32_t dst, const void* src) {
    asm volatile("cp.async.cg.shared.global [%0], [%1], 16;" :: "r"(dst), "l"(src));
}
#define CP_COMMIT() asm volatile("cp.async.commit_group;" ::: "memory")
#define CP_WAIT(n)  asm volatile("cp.async.wait_group %0;" :: "n"(n) : "memory")

// ---------------- split conversions -----------------------------------------
__global__ void split_f32_kernel(const float* __restrict__ src,
                                 __nv_bfloat16* __restrict__ dh,
                                 __nv_bfloat16* __restrict__ dl, int n) {
    int i = blockIdx.x * blockDim.x + threadIdx.x;
    if (i >= n) return;
    float y = src[i];
    __nv_bfloat16 h = __float2bfloat16(y);
    dh[i] = h;
    dl[i] = __float2bfloat16(y - __bfloat162float(h));
}

__global__ void split_weights_kernel(const float* __restrict__ Wq,
                                     const float* __restrict__ Wk,
                                     const float* __restrict__ Wv,
                                     const float* __restrict__ Wo) {
    const int nq = 2048 * Cc;
    const int nk = 512 * Cc;
    const int nqkv = nq + 2 * nk;
    const int ntot = nqkv + Cc * Cc;
    int idx = blockIdx.x * blockDim.x + threadIdx.x;
    if (idx >= ntot) return;
    float y;
    __nv_bfloat16* dh;
    __nv_bfloat16* dl;
    int o;
    if (idx < nq)               { y = Wq[idx];            dh = g_wh;  dl = g_wl;  o = idx; }
    else if (idx < nq + nk)     { y = Wk[idx - nq];       dh = g_wh;  dl = g_wl;  o = idx; }
    else if (idx < nqkv)        { y = Wv[idx - nq - nk];  dh = g_wh;  dl = g_wl;  o = idx; }
    else                        { y = Wo[idx - nqkv];     dh = g_woh; dl = g_wol; o = idx - nqkv; }
    __nv_bfloat16 h = __float2bfloat16(y);
    dh[o] = h;
    dl[o] = __float2bfloat16(y - __bfloat162float(h));
}

__global__ void postproc_kernel(float qscale) {
    const int N1 = Bb * Hh  * Tt * 64;
    const int N2 = Bb * KVh * Tt * 64;
    const int N3 = Bb * KVh * Tt * Dd;
    int idx = blockIdx.x * blockDim.x + threadIdx.x;
    if (idx < N1 + N2) {
        const float* src; __nv_bfloat16 *dh, *dl; float scale; int r;
        if (idx < N1) { src = g_q; dh = g_qh; dl = g_ql; scale = qscale; r = idx; }
        else          { src = g_k; dh = g_kh; dl = g_kl; scale = 1.0f;  r = idx - N1; }
        int d  = r & 63;
        int t  = (r >> 6) & (Tt - 1);
        int bh = r / (64 * Tt);
        float c = g_cos[t * 64 + d];
        float s = g_sin[t * 64 + d];
        size_t base = ((size_t)bh * Tt + t) * Dd;
        float x1 = src[base + d], x2 = src[base + d + 64];
        float y1 = (x1 * c - x2 * s) * scale;
        float y2 = (x2 * c + x1 * s) * scale;
        __nv_bfloat16 h1 = __float2bfloat16(y1);
        __nv_bfloat16 h2 = __float2bfloat16(y2);
        dh[base + d]      = h1;
        dh[base + d + 64] = h2;
        dl[base + d]      = __float2bfloat16(y1 - __bfloat162float(h1));
        dl[base + d + 64] = __float2bfloat16(y2 - __bfloat162float(h2));
    } else if (idx < N1 + N2 + N3) {
        int r = idx - N1 - N2;
        float y = g_v[r];
        __nv_bfloat16 h = __float2bfloat16(y);
        g_vh[r] = h;
        g_vl[r] = __float2bfloat16(y - __bfloat162float(h));
    }
}

// ======================= bf16 hi/lo GEMM (R11-proven, 2 CTAs/SM) ============
#define GLDH 40
#define GMAT (128 * GLDH * 2)
#define GSTG (4 * GMAT)

template <int MODE>
__global__ void __launch_bounds__(256, 2)
gemm_bf16_kernel(const __nv_bfloat16* __restrict__ Ah,
                 const __nv_bfloat16* __restrict__ Al,
                 const __nv_bfloat16* __restrict__ Bh,
                 const __nv_bfloat16* __restrict__ Bl,
                 float* __restrict__ Cq, float* __restrict__ Ck,
                 float* __restrict__ Cv, int M, int N, int K)
{
    extern __shared__ char smem[];
    const uint32_t sb = smem_u32_(smem);

    const int tid  = threadIdx.x;
    const int wid  = tid >> 5;
    const int lane = tid & 31;
    const int wr   = wid >> 2;
    const int wc   = wid & 3;
    const int m0   = blockIdx.y * 128;
    const int n0   = blockIdx.x * 128;

    const int lrow = tid >> 1;
    const int lc   = (tid & 1) * 16;
    const size_t aoff = (size_t)(m0 + lrow) * K + lc;
    const size_t boff = (size_t)(n0 + lrow) * K + lc;
    const uint32_t soff = (uint32_t)(lrow * GLDH + lc) * 2;

    auto load_stage = [&](int kk, int stg) {
        const uint32_t db = sb + stg * GSTG + soff;
        cp16(db + 0 * GMAT,      Ah + aoff + kk);
        cp16(db + 0 * GMAT + 16, Ah + aoff + kk + 8);
        cp16(db + 1 * GMAT,      Al + aoff + kk);
        cp16(db + 1 * GMAT + 16, Al + aoff + kk + 8);
        cp16(db + 2 * GMAT,      Bh + boff + kk);
        cp16(db + 2 * GMAT + 16, Bh + boff + kk + 8);
        cp16(db + 3 * GMAT,      Bl + boff + kk);
        cp16(db + 3 * GMAT + 16, Bl + boff + kk + 8);
    };

    float acc[4][4][4];
#pragma unroll
    for (int i = 0; i < 4; i++)
#pragma unroll
        for (int j = 0; j < 4; j++)
#pragma unroll
            for (int q = 0; q < 4; q++) acc[i][j][q] = 0.f;

    const int NC = K / 32;

    load_stage(0, 0);
    CP_COMMIT();

    const uint32_t a_row  = wr * 64 + (lane & 15);
    const uint32_t a_kh   = (lane >> 4) * 8;
    const uint32_t b_row2 = (lane & 7) + ((lane >> 4) * 8);
    const uint32_t b_kh   = ((lane >> 3) & 1) * 8;

    for (int i = 0; i < NC; i++) {
        if (i + 1 < NC) {
            load_stage((i + 1) * 32, (i + 1) & 1);
            CP_COMMIT();
            CP_WAIT(1);
        } else {
            CP_WAIT(0);
        }
        __syncthreads();

        const uint32_t stb = sb + (i & 1) * GSTG;
#pragma unroll
        for (int kstep = 0; kstep < 2; kstep++) {
            const uint32_t kof = kstep * 16;

            uint32_t bh[4][2], bl[4][2];
#pragma unroll
            for (int p = 0; p < 2; p++) {
                uint32_t bd = stb + ((wc * 32 + p * 16 + b_row2) * GLDH + kof + b_kh) * 2;
                ldsm_x4(bh[2*p][0], bh[2*p][1], bh[2*p+1][0], bh[2*p+1][1], bd + 2 * GMAT);
                ldsm_x4(bl[2*p][0], bl[2*p][1], bl[2*p+1][0], bl[2*p+1][1], bd + 3 * GMAT);
            }

            {
                uint32_t ahi[4][4];
#pragma unroll
                for (int mt = 0; mt < 4; mt++) {
                    uint32_t ad = stb + ((a_row + mt * 16) * GLDH + kof + a_kh) * 2;
                    ldsm_x4(ahi[mt][0], ahi[mt][1], ahi[mt][2], ahi[mt][3], ad + 0 * GMAT);
                }
#pragma unroll
                for (int mt = 0; mt < 4; mt++)
#pragma unroll
                    for (int nt = 0; nt < 4; nt++) {
                        mma16816b(acc[mt][nt], ahi[mt], bh[nt][0], bh[nt][1]);
                        mma16816b(acc[mt][nt], ahi[mt], bl[nt][0], bl[nt][1]);
                    }
            }
            {
                uint32_t alo[4][4];
#pragma unroll
                for (int mt = 0; mt < 4; mt++) {
                    uint32_t ad = stb + ((a_row + mt * 16) * GLDH + kof + a_kh) * 2;
                    ldsm_x4(alo[mt][0], alo[mt][1], alo[mt][2], alo[mt][3], ad + 1 * GMAT);
                }
#pragma unroll
                for (int mt = 0; mt < 4; mt++)
#pragma unroll
                    for (int nt = 0; nt < 4; nt++)
                        mma16816b(acc[mt][nt], alo[mt], bh[nt][0], bh[nt][1]);
            }
        }
        __syncthreads();
    }

#pragma unroll
    for (int mt = 0; mt < 4; mt++) {
        const int r0 = m0 + wr * 64 + mt * 16 + (lane >> 2);
        const int r1 = r0 + 8;
#pragma unroll
        for (int nt = 0; nt < 4; nt++) {
            const int c = n0 + wc * 32 + nt * 8 + (lane & 3) * 2;
            if (MODE == 0) {
                *(float2*)(Cq + (size_t)r0 * N + c) = make_float2(acc[mt][nt][0], acc[mt][nt][1]);
                *(float2*)(Cq + (size_t)r1 * N + c) = make_float2(acc[mt][nt][2], acc[mt][nt][3]);
            } else {
                const int b0_ = r0 / Tt, t0_ = r0 & (Tt - 1);
                const int b1_ = r1 / Tt, t1_ = r1 & (Tt - 1);
                float* d0;
                float* d1;
                if (c < 2048) {
                    const int h = c >> 7, d = c & 127;
                    d0 = Cq + (((size_t)b0_ * Hh + h) * Tt + t0_) * Dd + d;
                    d1 = Cq + (((size_t)b1_ * Hh + h) * Tt + t1_) * Dd + d;
                } else if (c < 2560) {
                    const int cc = c - 2048, h = cc >> 7, d = cc & 127;
                    d0 = Ck + (((size_t)b0_ * KVh + h) * Tt + t0_) * Dd + d;
                    d1 = Ck + (((size_t)b1_ * KVh + h) * Tt + t1_) * Dd + d;
                } else {
                    const int cc = c - 2560, h = cc >> 7, d = cc & 127;
                    d0 = Cv + (((size_t)b0_ * KVh + h) * Tt + t0_) * Dd + d;
                    d1 = Cv + (((size_t)b1_ * KVh + h) * Tt + t1_) * Dd + d;
                }
                *(float2*)d0 = make_float2(acc[mt][nt][0], acc[mt][nt][1]);
                *(float2*)d1 = make_float2(acc[mt][nt][2], acc[mt][nt][3]);
            }
        }
    }
}

// ================= HMMA flash attention, occ 2 (R11-proven) =================
// Epilogue change vs R11: writes bf16 hi/lo split output directly (g_ah/g_al),
// eliminating the fp32 g_att intermediate + separate split kernel.
#define FC_LDH  136
#define FC_ROW  (FC_LDH * 2)
#define FC_MAT  (64 * FC_ROW)
#define FC_STG  (4 * FC_MAT)
#define FC_QOFF FC_STG
#define FC_SMEM (FC_QOFF + 2 * FC_MAT) // 104448

__global__ void __launch_bounds__(128, 2)
flash_hmma3_kernel() {
    extern __shared__ char smem[];
    const uint32_t sb = smem_u32_(smem);

    const int it = (Tt / 64 - 1) - blockIdx.x;
    const int h  = blockIdx.y;
    const int b  = blockIdx.z;
    const int kvh = h / REP;

    const __nv_bfloat16* qh = g_qh + (((size_t)b * Hh + h) * Tt + it * 64) * Dd;
    const __nv_bfloat16* ql = g_ql + (((size_t)b * Hh + h) * Tt + it * 64) * Dd;
    const __nv_bfloat16* kh = g_kh + ((size_t)b * KVh + kvh) * Tt * Dd;
    const __nv_bfloat16* kl = g_kl + ((size_t)b * KVh + kvh) * Tt * Dd;
    const __nv_bfloat16* vh = g_vh + ((size_t)b * KVh + kvh) * Tt * Dd;
    const __nv_bfloat16* vl = g_vl + ((size_t)b * KVh + kvh) * Tt * Dd;

    const int tid  = threadIdx.x;
    const int wq   = tid >> 5;
    const int lane = tid & 31;

#pragma unroll
    for (int c = tid; c < 1024; c += 128) {
        const uint32_t d = sb + FC_QOFF + (c >> 4) * FC_ROW + (c & 15) * 16;
        const size_t  o = (size_t)(c >> 4) * Dd + (c & 15) * 8;
        cp16(d, qh + o);
        cp16(d + FC_MAT, ql + o);
    }
    CP_COMMIT();
    CP_WAIT(0);
    __syncthreads();

    uint32_t qfh[8][4], qfl[8][4];
    {
        const uint32_t qa = sb + FC_QOFF + (wq * 16 + (lane & 15)) * FC_ROW
                          + ((lane >> 4) * 8) * 2;
#pragma unroll
        for (int ks = 0; ks < 8; ks++) {
            uint32_t ad = qa + ks * 32;
            ldsm_x4(qfh[ks][0], qfh[ks][1], qfh[ks][2], qfh[ks][3], ad);
            ldsm_x4(qfl[ks][0], qfl[ks][1], qfl[ks][2], qfl[ks][3], ad + FC_MAT);
        }
    }

    float m_a = -1e30f, m_b = -1e30f, l_a = 0.f, l_b = 0.f;
    float oacc[16][4];
#pragma unroll
    for (int nt = 0; nt < 16; nt++)
#pragma unroll
        for (int q = 0; q < 4; q++) oacc[nt][q] = 0.f;

    const uint32_t kb_row = (lane & 7) + ((lane >> 4) * 8);
    const uint32_t kb_kh  = ((lane >> 3) & 1) * 8;
    const uint32_t vt_kv  = lane & 15;
    const uint32_t vt_dh  = (lane >> 4) * 8;

    for (int jt = 0; jt <= it; jt++) {
        __syncthreads();
#pragma unroll
        for (int c = tid; c < 1024; c += 128) {
            const uint32_t d = sb + (c >> 4) * FC_ROW + (c & 15) * 16;
            const size_t  o = (size_t)jt * 64 * Dd + (c >> 4) * Dd + (c & 15) * 8;
            cp16(d + 0 * FC_MAT, kh + o);
            cp16(d + 1 * FC_MAT, kl + o);
            cp16(d + 2 * FC_MAT, vh + o);
            cp16(d + 3 * FC_MAT, vl + o);
        }
        CP_COMMIT();
        CP_WAIT(0);
        __syncthreads();

        float sacc[8][4];
#pragma unroll
        for (int nt = 0; nt < 8; nt++)
#pragma unroll
            for (int q = 0; q < 4; q++) sacc[nt][q] = 0.f;

#pragma unroll
        for (int ks = 0; ks < 8; ks++) {
#pragma unroll
            for (int ntp = 0; ntp < 4; ntp++) {
                uint32_t bd = sb + ((ntp * 16 + kb_row) * FC_LDH + ks * 16 + kb_kh) * 2;
                uint32_t k0, k1, k2, k3, c0, c1, c2, c3;
                ldsm_x4(k0, k1, k2, k3, bd + 0 * FC_MAT);
                ldsm_x4(c0, c1, c2, c3, bd + 1 * FC_MAT);
                mma16816b(sacc[2*ntp],   qfh[ks], k0, k1);
                mma16816b(sacc[2*ntp],   qfh[ks], c0, c1);
                mma16816b(sacc[2*ntp],   qfl[ks], k0, k1);
                mma16816b(sacc[2*ntp+1], qfh[ks], k2, k3);
                mma16816b(sacc[2*ntp+1], qfh[ks], c2, c3);
                mma16816b(sacc[2*ntp+1], qfl[ks], k2, k3);
            }
        }

        if (jt == it) {
            const int ra = wq * 16 + (lane >> 2);
            const int cb = (lane & 3) * 2;
#pragma unroll
            for (int nt = 0; nt < 8; nt++) {
                const int c0 = cb + nt * 8;
                if (c0 > ra)         sacc[nt][0] = -1e30f;
                if (c0 + 1 > ra)     sacc[nt][1] = -1e30f;
                if (c0 > ra + 8)     sacc[nt][2] = -1e30f;
                if (c0 + 1 > ra + 8) sacc[nt][3] = -1e30f;
            }
        }

        float mx_a = -1e30f, mx_b = -1e30f;
#pragma unroll
        for (int nt = 0; nt < 8; nt++) {
            mx_a = fmaxf(mx_a, fmaxf(sacc[nt][0], sacc[nt][1]));
            mx_b = fmaxf(mx_b, fmaxf(sacc[nt][2], sacc[nt][3]));
        }
        mx_a = fmaxf(mx_a, __shfl_xor_sync(0xffffffffu, mx_a, 1));
        mx_a = fmaxf(mx_a, __shfl_xor_sync(0xffffffffu, mx_a, 2));
        mx_b = fmaxf(mx_b, __shfl_xor_sync(0xffffffffu, mx_b, 1));
        mx_b = fmaxf(mx_b, __shfl_xor_sync(0xffffffffu, mx_b, 2));

        const float mn_a = fmaxf(m_a, mx_a);
        const float mn_b = fmaxf(m_b, mx_b);
        const float al_a = exp2f(m_a - mn_a);
        const float al_b = exp2f(m_b - mn_b);
        m_a = mn_a; m_b = mn_b;

        float ls_a = 0.f, ls_b = 0.f;
#pragma unroll
        for (int nt = 0; nt < 8; nt++) {
            float p0 = exp2f(sacc[nt][0] - mn_a);
            float p1 = exp2f(sacc[nt][1] - mn_a);
            float p2 = exp2f(sacc[nt][2] - mn_b);
            float p3 = exp2f(sacc[nt][3] - mn_b);
            sacc[nt][0] = p0; sacc[nt][1] = p1; sacc[nt][2] = p2; sacc[nt][3] = p3;
            ls_a += p0 + p1; ls_b += p2 + p3;
        }
        ls_a += __shfl_xor_sync(0xffffffffu, ls_a, 1);
        ls_a += __shfl_xor_sync(0xffffffffu, ls_a, 2);
        ls_b += __shfl_xor_sync(0xffffffffu, ls_b, 1);
        ls_b += __shfl_xor_sync(0xffffffffu, ls_b, 2);
        l_a = l_a * al_a + ls_a;
        l_b = l_b * al_b + ls_b;

#pragma unroll
        for (int nt = 0; nt < 16; nt++) {
            oacc[nt][0] *= al_a; oacc[nt][1] *= al_a;
            oacc[nt][2] *= al_b; oacc[nt][3] *= al_b;
        }

#pragma unroll
        for (int kt = 0; kt < 4; kt++) {
            uint32_t phi[4], plo[4];
            {
                float* pa = sacc[2*kt];
                float* pb = sacc[2*kt + 1];
                __nv_bfloat16 e0, e1;
                e0 = __float2bfloat16(pa[0]); e1 = __float2bfloat16(pa[1]);
                phi[0] = ((uint32_t)__bfloat16_as_ushort(e1) << 16) | __bfloat16_as_ushort(e0);
                plo[0] = pack_bf16x2(pa[0] - __bfloat162float(e0), pa[1] - __bfloat162float(e1));
                e0 = __float2bfloat16(pa[2]); e1 = __float2bfloat16(pa[3]);
                phi[1] = ((uint32_t)__bfloat16_as_ushort(e1) << 16) | __bfloat16_as_ushort(e0);
                plo[1] = pack_bf16x2(pa[2] - __bfloat162float(e0), pa[3] - __bfloat162float(e1));
                e0 = __float2bfloat16(pb[0]); e1 = __float2bfloat16(pb[1]);
                phi[2] = ((uint32_t)__bfloat16_as_ushort(e1) << 16) | __bfloat16_as_ushort(e0);
                plo[2] = pack_bf16x2(pb[0] - __bfloat162float(e0), pb[1] - __bfloat162float(e1));
                e0 = __float2bfloat16(pb[2]); e1 = __float2bfloat16(pb[3]);
                phi[3] = ((uint32_t)__bfloat16_as_ushort(e1) << 16) | __bfloat16_as_ushort(e0);
                plo[3] = pack_bf16x2(pb[2] - __bfloat162float(e0), pb[3] - __bfloat162float(e1));
            }
#pragma unroll
            for (int ntp = 0; ntp < 8; ntp++) {
                uint32_t vd = sb + ((kt * 16 + vt_kv) * FC_LDH + ntp * 16 + vt_dh) * 2;
                uint32_t v0, v1, v2, v3, w0, w1, w2, w3;
                ldsm_x4_t(v0, v1, v2, v3, vd + 2 * FC_MAT);
                ldsm_x4_t(w0, w1, w2, w3, vd + 3 * FC_MAT);
                mma16816b(oacc[2*ntp],   phi, v0, v1);
                mma16816b(oacc[2*ntp],   phi, w0, w1);
                mma16816b(oacc[2*ntp],   plo, v0, v1);
                mma16816b(oacc[2*ntp+1], phi, v2, v3);
                mma16816b(oacc[2*ntp+1], phi, w2, w3);
                mma16816b(oacc[2*ntp+1], plo, v2, v3);
            }
        }
    }

    // ---- finalize: divide by l, split to bf16 hi/lo, write g_ah/g_al -------
    const float inv_a = 1.f / l_a;
    const float inv_b = 1.f / l_b;
    const int ta = it * 64 + wq * 16 + (lane >> 2);
    const int tb = ta + 8;
    const size_t oa = ((size_t)b * Tt + ta) * Cc + h * Dd;
    const size_t ob = ((size_t)b * Tt + tb) * Cc + h * Dd;
#pragma unroll
    for (int nt = 0; nt < 16; nt++) {
        const int d = nt * 8 + (lane & 3) * 2;
        float va0 = oacc[nt][0] * inv_a, va1 = oacc[nt][1] * inv_a;
        float vb0 = oacc[nt][2] * inv_b, vb1 = oacc[nt][3] * inv_b;
        __nv_bfloat16 ha0 = __float2bfloat16(va0), ha1 = __float2bfloat16(va1);
        __nv_bfloat16 hb0 = __float2bfloat16(vb0), hb1 = __float2bfloat16(vb1);
        uint32_t pa_h = ((uint32_t)__bfloat16_as_ushort(ha1) << 16) | __bfloat16_as_ushort(ha0);
        uint32_t pb_h = ((uint32_t)__bfloat16_as_ushort(hb1) << 16) | __bfloat16_as_ushort(hb0);
        uint32_t pa_l = pack_bf16x2(va0 - __bfloat162float(ha0), va1 - __bfloat162float(ha1));
        uint32_t pb_l = pack_bf16x2(vb0 - __bfloat162float(hb0), vb1 - __bfloat162float(hb1));
        *(uint32_t*)(g_ah + oa + d) = pa_h;
        *(uint32_t*)(g_al + oa + d) = pa_l;
        *(uint32_t*)(g_ah + ob + d) = pb_h;
        *(uint32_t*)(g_al + ob + d) = pb_l;
    }
}

// ---------------- launch ----------------------------------------------------
extern "C" void kernel_launch(void* const* d_in, const int* in_sizes, int n_in,
                              void* d_out, int out_size) {
    const float* x  = (const float*)d_in[0];
    const float* Wq = (const float*)d_in[1];
    const float* Wk = (const float*)d_in[2];
    const float* Wv = (const float*)d_in[3];
    const float* Wo = (const float*)d_in[4];
    float* out = (float*)d_out;

    float *pq, *pk, *pv;
    cudaGetSymbolAddress((void**)&pq, g_q);
    cudaGetSymbolAddress((void**)&pk, g_k);
    cudaGetSymbolAddress((void**)&pv, g_v);
    __nv_bfloat16 *pxh, *pxl, *pwh, *pwl, *pwoh, *pwol, *pah, *pal;
    cudaGetSymbolAddress((void**)&pxh, g_xh);
    cudaGetSymbolAddress((void**)&pxl, g_xl);
    cudaGetSymbolAddress((void**)&pwh, g_wh);
    cudaGetSymbolAddress((void**)&pwl, g_wl);
    cudaGetSymbolAddress((void**)&pwoh, g_woh);
    cudaGetSymbolAddress((void**)&pwol, g_wol);
    cudaGetSymbolAddress((void**)&pah, g_ah);
    cudaGetSymbolAddress((void**)&pal, g_al);

    const int M = Bb * Tt;                 // 4096
    const int gemm_smem = 2 * GSTG;        // 81920
    cudaFuncSetAttribute(gemm_bf16_kernel<0>,
                         cudaFuncAttributeMaxDynamicSharedMemorySize, gemm_smem);
    cudaFuncSetAttribute(gemm_bf16_kernel<1>,
                         cudaFuncAttributeMaxDynamicSharedMemorySize, gemm_smem);
    cudaFuncSetAttribute(flash_hmma3_kernel,
                         cudaFuncAttributeMaxDynamicSharedMemorySize, FC_SMEM);

    const int nx = M * Cc;
    const float qscale = 0.08838834764831845f * 1.4426950408889634f;

    // launch 0: split x
    split_f32_kernel<<<(nx + 255) / 256, 256>>>(x, pxh, pxl, nx);
    // launch 1: split all weights
    split_weights_kernel<<<((NQKV * Cc + Cc * Cc) + 255) / 256, 256>>>(Wq, Wk, Wv, Wo);
    // launch 2: rope tables
    rope_tables_kernel<<<(Tt * 64 + 255) / 256, 256>>>();
    // launch 3: fused QKV projection (R11-proven 256-thread GEMM)
    gemm_bf16_kernel<1><<<dim3(NQKV / 128, M / 128), 256, gemm_smem>>>(
        pxh, pxl, pwh, pwl, pq, pk, pv, M, NQKV, Cc);
    // launch 4: rope + split q/k, split v
    postproc_kernel<<<((Bb*Hh*Tt*64 + Bb*KVh*Tt*64 + Bb*KVh*Tt*Dd) + 255) / 256, 256>>>(qscale);
    // launch 5: flash attention (writes bf16 hi/lo output directly)
    flash_hmma3_kernel<<<dim3(Tt / 64, Hh, Bb), 128, FC_SMEM>>>();
    // launch 6: output projection (no intermediate split needed)
    gemm_bf16_kernel<0><<<dim3(Cc / 128, M / 128), 256, gemm_smem>>>(
        pah, pal, pwoh, pwol, out, nullptr, nullptr, M, Cc, Cc);
}